// round 1
// baseline (speedup 1.0000x reference)
#include <cuda_runtime.h>
#include <math.h>

// Problem constants
#define BATCH 8
#define SEQ   512
#define HDIM  1024
#define FFDIM 4096
#define NHEAD 16
#define DHEAD 64
#define MROWS (BATCH*SEQ)   // 4096

// ---------------------------------------------------------------------------
// Static device scratch (no allocations allowed in kernel_launch)
// ---------------------------------------------------------------------------
__device__ float g_q[(size_t)MROWS * HDIM];
__device__ float g_k[(size_t)MROWS * HDIM];
__device__ float g_v[(size_t)MROWS * HDIM];
__device__ float g_ctx[(size_t)MROWS * HDIM];
__device__ float g_t1[(size_t)MROWS * HDIM];
__device__ float g_attn[(size_t)MROWS * HDIM];
__device__ float g_inter[(size_t)MROWS * FFDIM];

// ---------------------------------------------------------------------------
// GELU (BERT tanh approximation, matches jax.nn.gelu approximate=True)
// ---------------------------------------------------------------------------
__device__ __forceinline__ float gelu_tanh(float x) {
    float x3 = x * x * x;
    return 0.5f * x * (1.0f + tanhf(0.7978845608028654f * (x + 0.044715f * x3)));
}

// ---------------------------------------------------------------------------
// SGEMM: C[M,N] = A[M,K] @ B[K,N] + bias[N] (+ residual[M,N]) (optional GELU)
// BM=BN=128, BK=8, 256 threads, 8x8 per-thread micro-tile.
// REQUIRES: M%128==0, N%128==0, K%8==0 (true for all calls here).
// ---------------------------------------------------------------------------
#define BM 128
#define BN 128
#define BK 8

__global__ __launch_bounds__(256)
void sgemm_kernel(const float* __restrict__ A, const float* __restrict__ B,
                  const float* __restrict__ bias, const float* __restrict__ res,
                  float* __restrict__ C, int M, int N, int K, int do_gelu)
{
    __shared__ __align__(16) float As[BK][BM];
    __shared__ __align__(16) float Bs[BK][BN];

    const int t  = threadIdx.x;            // 0..255
    const int bx = blockIdx.x, by = blockIdx.y;
    const int row0 = by * BM, col0 = bx * BN;

    // A tile loader: thread -> (m = t/2, k4 = (t&1)*4), float4 along K
    const int a_m = t >> 1;
    const int a_k = (t & 1) * 4;
    // B tile loader: thread -> (k = t/32, n4 = (t&31)*4), float4 along N
    const int b_k = t >> 5;
    const int b_n = (t & 31) * 4;

    const float* Aptr = A + (size_t)(row0 + a_m) * K + a_k;
    const float* Bptr = B + (size_t)b_k * N + col0 + b_n;

    const int tx = t & 15;   // 0..15 -> col micro-tile
    const int ty = t >> 4;   // 0..15 -> row micro-tile

    float acc[8][8];
    #pragma unroll
    for (int i = 0; i < 8; i++)
        #pragma unroll
        for (int j = 0; j < 8; j++) acc[i][j] = 0.0f;

    for (int k0 = 0; k0 < K; k0 += BK) {
        float4 av = *(const float4*)(Aptr + k0);
        float4 bv = *(const float4*)(Bptr + (size_t)k0 * N);
        As[a_k + 0][a_m] = av.x;
        As[a_k + 1][a_m] = av.y;
        As[a_k + 2][a_m] = av.z;
        As[a_k + 3][a_m] = av.w;
        *(float4*)&Bs[b_k][b_n] = bv;
        __syncthreads();

        #pragma unroll
        for (int k = 0; k < BK; k++) {
            float a[8], b[8];
            #pragma unroll
            for (int i = 0; i < 8; i++) a[i] = As[k][ty * 8 + i];
            #pragma unroll
            for (int j = 0; j < 8; j++) b[j] = Bs[k][tx * 8 + j];
            #pragma unroll
            for (int i = 0; i < 8; i++)
                #pragma unroll
                for (int j = 0; j < 8; j++)
                    acc[i][j] = fmaf(a[i], b[j], acc[i][j]);
        }
        __syncthreads();
    }

    // Epilogue
    #pragma unroll
    for (int i = 0; i < 8; i++) {
        int r = row0 + ty * 8 + i;
        #pragma unroll
        for (int j = 0; j < 8; j++) {
            int c = col0 + tx * 8 + j;
            float v = acc[i][j] + bias[c];
            if (res) v += res[(size_t)r * N + c];
            if (do_gelu) v = gelu_tanh(v);
            C[(size_t)r * N + c] = v;
        }
    }
}

// ---------------------------------------------------------------------------
// Fused flash attention (fp32, online softmax).
// Grid: (SEQ/64, NHEAD, BATCH). Block: 256 threads.
// Thread t owns q = t/4 (local query row) and part = t%4
//   - scores phase: part = 16-key slice
//   - PV phase:     part = 16-dim slice of the head dim
// Dynamic smem: Qs/Ks/Vs/Ps, 64 x 68-float rows (pad for banks) = 69632 B.
// ---------------------------------------------------------------------------
#define ALD 68

__global__ __launch_bounds__(256)
void attn_kernel(const float* __restrict__ Q, const float* __restrict__ Kg,
                 const float* __restrict__ Vg, const int* __restrict__ mask,
                 float* __restrict__ O)
{
    extern __shared__ float sm[];
    float* Qs = sm;
    float* Ks = sm + 64 * ALD;
    float* Vs = sm + 2 * 64 * ALD;
    float* Ps = sm + 3 * 64 * ALD;

    const int t = threadIdx.x;
    const int b = blockIdx.z, h = blockIdx.y;
    const int q0 = blockIdx.x * 64;
    const int q    = t >> 2;   // 0..63
    const int part = t & 3;    // 0..3

    // load Q tile (each thread: one row, 16 contiguous floats)
    {
        const int i = t >> 2, d0 = (t & 3) * 16;
        const float* src = Q + ((size_t)(b * SEQ + q0 + i)) * HDIM + h * DHEAD + d0;
        #pragma unroll
        for (int j = 0; j < 16; j++) Qs[i * ALD + d0 + j] = src[j];
    }

    float acc[16];
    #pragma unroll
    for (int i = 0; i < 16; i++) acc[i] = 0.0f;
    float m_run = -1e30f, l_run = 0.0f;

    const int* mrow = mask + ((size_t)(b * SEQ + q0 + q)) * SEQ;

    for (int kc = 0; kc < SEQ; kc += 64) {
        __syncthreads();  // protect Ks/Vs/Ps from previous iteration
        {
            const int i = t >> 2, d0 = (t & 3) * 16;
            const float* ks = Kg + ((size_t)(b * SEQ + kc + i)) * HDIM + h * DHEAD + d0;
            const float* vs = Vg + ((size_t)(b * SEQ + kc + i)) * HDIM + h * DHEAD + d0;
            #pragma unroll
            for (int j = 0; j < 16; j++) {
                Ks[i * ALD + d0 + j] = ks[j];
                Vs[i * ALD + d0 + j] = vs[j];
            }
        }
        __syncthreads();

        // scores for keys [part*16, part*16+16)
        float s[16];
        #pragma unroll
        for (int kk = 0; kk < 16; kk++) s[kk] = 0.0f;
        #pragma unroll
        for (int d0 = 0; d0 < 64; d0 += 16) {
            float4 qv[4];
            #pragma unroll
            for (int u = 0; u < 4; u++)
                qv[u] = *(const float4*)&Qs[q * ALD + d0 + 4 * u];
            #pragma unroll
            for (int kk = 0; kk < 16; kk++) {
                const int k = part * 16 + kk;
                float p = 0.0f;
                #pragma unroll
                for (int u = 0; u < 4; u++) {
                    float4 kv = *(const float4*)&Ks[k * ALD + d0 + 4 * u];
                    p += qv[u].x * kv.x + qv[u].y * kv.y + qv[u].z * kv.z + qv[u].w * kv.w;
                }
                s[kk] += p;
            }
        }

        // scale + additive mask, chunk max
        float cmax = -1e30f;
        #pragma unroll
        for (int kk = 0; kk < 16; kk++) {
            const int k = part * 16 + kk;
            float add = (1.0f - (float)mrow[kc + k]) * -10000.0f;
            s[kk] = s[kk] * 0.125f + add;   // 1/sqrt(64) = 0.125
            cmax = fmaxf(cmax, s[kk]);
        }
        cmax = fmaxf(cmax, __shfl_xor_sync(0xffffffffu, cmax, 1));
        cmax = fmaxf(cmax, __shfl_xor_sync(0xffffffffu, cmax, 2));

        const float m_new = fmaxf(m_run, cmax);
        const float alpha = __expf(m_run - m_new);
        float psum = 0.0f;
        #pragma unroll
        for (int kk = 0; kk < 16; kk++) {
            float p = __expf(s[kk] - m_new);
            Ps[q * ALD + part * 16 + kk] = p;
            psum += p;
        }
        psum += __shfl_xor_sync(0xffffffffu, psum, 1);
        psum += __shfl_xor_sync(0xffffffffu, psum, 2);
        l_run = l_run * alpha + psum;
        m_run = m_new;
        __syncwarp();  // Ps produced/consumed within the same warp's 4-groups

        // acc update: this thread owns dims [part*16, part*16+16)
        #pragma unroll
        for (int i = 0; i < 16; i++) acc[i] *= alpha;
        const int dbase = part * 16;
        #pragma unroll
        for (int k = 0; k < 64; k++) {
            const float p = Ps[q * ALD + k];
            #pragma unroll
            for (int u = 0; u < 4; u++) {
                float4 vv = *(const float4*)&Vs[k * ALD + dbase + 4 * u];
                acc[4 * u + 0] = fmaf(p, vv.x, acc[4 * u + 0]);
                acc[4 * u + 1] = fmaf(p, vv.y, acc[4 * u + 1]);
                acc[4 * u + 2] = fmaf(p, vv.z, acc[4 * u + 2]);
                acc[4 * u + 3] = fmaf(p, vv.w, acc[4 * u + 3]);
            }
        }
    }

    const float inv_l = 1.0f / l_run;
    float* dst = O + ((size_t)(b * SEQ + q0 + q)) * HDIM + h * DHEAD + part * 16;
    #pragma unroll
    for (int i = 0; i < 16; i++) dst[i] = acc[i] * inv_l;
}

// ---------------------------------------------------------------------------
// LayerNorm over rows of HDIM=1024. One block (256 threads) per row.
// y = (x - mean) * rsqrt(var + 1e-12) * gamma + beta
// ---------------------------------------------------------------------------
__global__ __launch_bounds__(256)
void ln_kernel(const float* __restrict__ x, const float* __restrict__ gamma,
               const float* __restrict__ beta, float* __restrict__ y)
{
    const int row = blockIdx.x;
    const int t = threadIdx.x;
    const float* xr = x + (size_t)row * HDIM;

    float4 v = *(const float4*)(xr + t * 4);
    float s  = v.x + v.y + v.z + v.w;
    float s2 = v.x * v.x + v.y * v.y + v.z * v.z + v.w * v.w;

    #pragma unroll
    for (int o = 16; o > 0; o >>= 1) {
        s  += __shfl_xor_sync(0xffffffffu, s, o);
        s2 += __shfl_xor_sync(0xffffffffu, s2, o);
    }
    __shared__ float ws[8], ws2[8];
    const int w = t >> 5, lane = t & 31;
    if (lane == 0) { ws[w] = s; ws2[w] = s2; }
    __syncthreads();

    float ts = 0.0f, ts2 = 0.0f;
    #pragma unroll
    for (int i = 0; i < 8; i++) { ts += ws[i]; ts2 += ws2[i]; }

    const float mean = ts * (1.0f / HDIM);
    const float var  = ts2 * (1.0f / HDIM) - mean * mean;
    const float rstd = rsqrtf(var + 1e-12f);

    float4 g  = *(const float4*)(gamma + t * 4);
    float4 bb = *(const float4*)(beta  + t * 4);
    float4 o;
    o.x = (v.x - mean) * rstd * g.x + bb.x;
    o.y = (v.y - mean) * rstd * g.y + bb.y;
    o.z = (v.z - mean) * rstd * g.z + bb.z;
    o.w = (v.w - mean) * rstd * g.w + bb.w;
    *(float4*)(y + (size_t)row * HDIM + t * 4) = o;
}

// ---------------------------------------------------------------------------
// Orchestration
// ---------------------------------------------------------------------------
extern "C" void kernel_launch(void* const* d_in, const int* in_sizes, int n_in,
                              void* d_out, int out_size)
{
    (void)in_sizes; (void)n_in; (void)out_size;

    const float* inp    = (const float*)d_in[0];
    const int*   mask   = (const int*)  d_in[1];
    const float* Wq     = (const float*)d_in[2];
    const float* bq     = (const float*)d_in[3];
    const float* Wk     = (const float*)d_in[4];
    const float* bk     = (const float*)d_in[5];
    const float* Wv     = (const float*)d_in[6];
    const float* bv     = (const float*)d_in[7];
    const float* Wao    = (const float*)d_in[8];
    const float* bao    = (const float*)d_in[9];
    const float* gamma1 = (const float*)d_in[10];
    const float* beta1  = (const float*)d_in[11];
    const float* Wi     = (const float*)d_in[12];
    const float* bi     = (const float*)d_in[13];
    const float* Wo     = (const float*)d_in[14];
    const float* bo     = (const float*)d_in[15];
    const float* gamma2 = (const float*)d_in[16];
    const float* beta2  = (const float*)d_in[17];
    float* out = (float*)d_out;

    float *q, *k, *v, *ctx, *t1, *attn, *inter;
    cudaGetSymbolAddress((void**)&q,     g_q);
    cudaGetSymbolAddress((void**)&k,     g_k);
    cudaGetSymbolAddress((void**)&v,     g_v);
    cudaGetSymbolAddress((void**)&ctx,   g_ctx);
    cudaGetSymbolAddress((void**)&t1,    g_t1);
    cudaGetSymbolAddress((void**)&attn,  g_attn);
    cudaGetSymbolAddress((void**)&inter, g_inter);

    const int ATTN_SMEM = 4 * 64 * ALD * (int)sizeof(float);  // 69632 B
    cudaFuncSetAttribute(attn_kernel, cudaFuncAttributeMaxDynamicSharedMemorySize,
                         ATTN_SMEM);

    dim3 blk(256);
    dim3 grid_h(HDIM / BN, MROWS / BM);   // N=1024
    dim3 grid_ff(FFDIM / BN, MROWS / BM); // N=4096

    // QKV projections
    sgemm_kernel<<<grid_h, blk>>>(inp, Wq, bq, nullptr, q, MROWS, HDIM, HDIM, 0);
    sgemm_kernel<<<grid_h, blk>>>(inp, Wk, bk, nullptr, k, MROWS, HDIM, HDIM, 0);
    sgemm_kernel<<<grid_h, blk>>>(inp, Wv, bv, nullptr, v, MROWS, HDIM, HDIM, 0);

    // Fused attention -> ctx
    attn_kernel<<<dim3(SEQ / 64, NHEAD, BATCH), blk, ATTN_SMEM>>>(q, k, v, mask, ctx);

    // Attention output projection + residual, then LN1
    sgemm_kernel<<<grid_h, blk>>>(ctx, Wao, bao, inp, t1, MROWS, HDIM, HDIM, 0);
    ln_kernel<<<MROWS, blk>>>(t1, gamma1, beta1, attn);

    // FFN
    sgemm_kernel<<<grid_ff, blk>>>(attn, Wi, bi, nullptr, inter, MROWS, FFDIM, HDIM, 1);
    sgemm_kernel<<<grid_h, blk>>>(inter, Wo, bo, attn, t1, MROWS, HDIM, FFDIM, 0);
    ln_kernel<<<MROWS, blk>>>(t1, gamma2, beta2, out);
}

// round 3
// speedup vs baseline: 1.7104x; 1.7104x over previous
#include <cuda_runtime.h>
#include <cuda_bf16.h>
#include <math.h>
#include <stdint.h>

#define BATCH 8
#define SEQ   512
#define HDIM  1024
#define FFDIM 4096
#define NHEAD 16
#define DHEAD 64
#define MROWS (BATCH*SEQ)   // 4096

// ---------------------------------------------------------------------------
// Static device scratch
// ---------------------------------------------------------------------------
__device__ float g_q[(size_t)MROWS * HDIM];
__device__ float g_k[(size_t)MROWS * HDIM];
__device__ float g_v[(size_t)MROWS * HDIM];
__device__ float g_ctx[(size_t)MROWS * HDIM];
__device__ float g_t1[(size_t)MROWS * HDIM];
__device__ float g_attn[(size_t)MROWS * HDIM];
__device__ float g_inter[(size_t)MROWS * FFDIM];

// bf16 hi/lo activation splits
__device__ __nv_bfloat16 g_xh[(size_t)MROWS * HDIM],  g_xl[(size_t)MROWS * HDIM];
__device__ __nv_bfloat16 g_ch[(size_t)MROWS * HDIM],  g_cl[(size_t)MROWS * HDIM];
__device__ __nv_bfloat16 g_ah[(size_t)MROWS * HDIM],  g_al[(size_t)MROWS * HDIM];
__device__ __nv_bfloat16 g_ih[(size_t)MROWS * FFDIM], g_il[(size_t)MROWS * FFDIM];
// transposed weight splits, [N, K]
__device__ __nv_bfloat16 g_wqh[(size_t)HDIM * HDIM],  g_wql[(size_t)HDIM * HDIM];
__device__ __nv_bfloat16 g_wkh[(size_t)HDIM * HDIM],  g_wkl[(size_t)HDIM * HDIM];
__device__ __nv_bfloat16 g_wvh[(size_t)HDIM * HDIM],  g_wvl[(size_t)HDIM * HDIM];
__device__ __nv_bfloat16 g_waoh[(size_t)HDIM * HDIM], g_waol[(size_t)HDIM * HDIM];
__device__ __nv_bfloat16 g_wih[(size_t)FFDIM * HDIM], g_wil[(size_t)FFDIM * HDIM];
__device__ __nv_bfloat16 g_woh[(size_t)HDIM * FFDIM], g_wol[(size_t)HDIM * FFDIM];

__device__ __forceinline__ float gelu_tanh(float x) {
    float x3 = x * x * x;
    return 0.5f * x * (1.0f + tanhf(0.7978845608028654f * (x + 0.044715f * x3)));
}

// ---------------------------------------------------------------------------
// PTX helpers (sm_80-era: legal on base sm_103 target)
// ---------------------------------------------------------------------------
__device__ __forceinline__ uint32_t smem_u32(const void* p) {
    uint32_t a;
    asm("{ .reg .u64 t; cvta.to.shared.u64 t, %1; cvt.u32.u64 %0, t; }"
        : "=r"(a) : "l"(p));
    return a;
}
__device__ __forceinline__ void cp16(uint32_t saddr, const void* gaddr) {
    asm volatile("cp.async.cg.shared.global [%0], [%1], 16;" :: "r"(saddr), "l"(gaddr));
}
#define CP_COMMIT() asm volatile("cp.async.commit_group;" ::: "memory")
#define CP_WAIT(n)  asm volatile("cp.async.wait_group %0;" :: "n"(n) : "memory")

__device__ __forceinline__ void ldm_x4(uint32_t* r, uint32_t addr) {
    asm volatile("ldmatrix.sync.aligned.m8n8.x4.shared.b16 {%0,%1,%2,%3}, [%4];"
        : "=r"(r[0]), "=r"(r[1]), "=r"(r[2]), "=r"(r[3]) : "r"(addr));
}
__device__ __forceinline__ void mma_bf16(float* c, const uint32_t* a, const uint32_t* b) {
    asm volatile(
        "mma.sync.aligned.m16n8k16.row.col.f32.bf16.bf16.f32 "
        "{%0,%1,%2,%3}, {%4,%5,%6,%7}, {%8,%9}, {%0,%1,%2,%3};"
        : "+f"(c[0]), "+f"(c[1]), "+f"(c[2]), "+f"(c[3])
        : "r"(a[0]), "r"(a[1]), "r"(a[2]), "r"(a[3]), "r"(b[0]), "r"(b[1]));
}

// ---------------------------------------------------------------------------
// Elementwise fp32 -> (bf16 hi, bf16 lo)
// ---------------------------------------------------------------------------
__global__ __launch_bounds__(256)
void split_kernel(const float* __restrict__ x, __nv_bfloat16* __restrict__ hi,
                  __nv_bfloat16* __restrict__ lo, int n4)
{
    int i = blockIdx.x * blockDim.x + threadIdx.x;
    if (i >= n4) return;
    float4 v = ((const float4*)x)[i];
    union { __nv_bfloat16 h[4]; uint2 u; } ph, pl;
    float f[4] = {v.x, v.y, v.z, v.w};
    #pragma unroll
    for (int j = 0; j < 4; j++) {
        __nv_bfloat16 h = __float2bfloat16(f[j]);
        ph.h[j] = h;
        pl.h[j] = __float2bfloat16(f[j] - __bfloat162float(h));
    }
    ((uint2*)hi)[i] = ph.u;
    ((uint2*)lo)[i] = pl.u;
}

// ---------------------------------------------------------------------------
// W[K,N] fp32 -> T[N,K] bf16 hi/lo (tiled transpose)
// ---------------------------------------------------------------------------
__global__ __launch_bounds__(256)
void transpose_split_kernel(const float* __restrict__ W, __nv_bfloat16* __restrict__ Th,
                            __nv_bfloat16* __restrict__ Tl, int K, int N)
{
    __shared__ float tile[32][33];
    int x = blockIdx.x * 32 + threadIdx.x;     // n
    int y0 = blockIdx.y * 32;                  // k base
    #pragma unroll
    for (int j = 0; j < 32; j += 8)
        tile[threadIdx.y + j][threadIdx.x] = W[(size_t)(y0 + threadIdx.y + j) * N + x];
    __syncthreads();
    int k = y0 + threadIdx.x;
    #pragma unroll
    for (int j = 0; j < 32; j += 8) {
        int n = blockIdx.x * 32 + threadIdx.y + j;
        float v = tile[threadIdx.x][threadIdx.y + j];
        __nv_bfloat16 h = __float2bfloat16(v);
        Th[(size_t)n * K + k] = h;
        Tl[(size_t)n * K + k] = __float2bfloat16(v - __bfloat162float(h));
    }
}

// ---------------------------------------------------------------------------
// bf16 split-GEMM via mma.sync: C[M,N] = (Ah+Al)[M,K] @ (Bh+Bl)[N,K]^T
//                                        + bias (+res) (gelu)
// CTA 128x128, 8 warps (2x4), warp tile 64x32. K-chunk 32, cp.async double buf.
// SMEM per buffer: 4 tiles (Ah,Al,Bh,Bl), each 128 rows x 40 bf16 (pad 8).
// ---------------------------------------------------------------------------
#define KC 32
#define LDSS 40                                 // padded stride (elements)
#define TILE_B (128 * LDSS * 2)                 // 10240 bytes per tile
#define BUF_B  (4 * TILE_B)                     // 40960 bytes per stage
#define GEMM_SMEM (2 * BUF_B)                   // 81920 bytes

__global__ __launch_bounds__(256, 2)
void mma_gemm(const __nv_bfloat16* __restrict__ Ah, const __nv_bfloat16* __restrict__ Al,
              const __nv_bfloat16* __restrict__ Bh, const __nv_bfloat16* __restrict__ Bl,
              const float* __restrict__ bias, const float* __restrict__ res,
              float* __restrict__ C, int M, int N, int K, int do_gelu)
{
    extern __shared__ char sm[];
    const uint32_t sbase = smem_u32(sm);

    const int t    = threadIdx.x;
    const int lane = t & 31;
    const int w    = t >> 5;          // 0..7
    const int wm   = w & 1;           // 2 row groups
    const int wn   = w >> 1;          // 4 col groups
    const int row0 = blockIdx.y * 128;
    const int col0 = blockIdx.x * 128;

    const __nv_bfloat16* srcs[4] = { Ah, Al, Bh, Bl };
    const int rb[4] = { row0, row0, col0, col0 };

    // cp.async slot mapping: per tile, slot s in {t, t+256}: row=s>>2, c16=s&3
    const int r_lo = t >> 2, c16 = t & 3;

    const int NC = K / KC;

    // fragment smem addresses (lane-dependent parts precomputed)
    // A frag (x4): row = wm*64 + mt*16 + (lane&15), col = ks*16 + (lane>>4)*8
    const int a_row = wm * 64 + (lane & 15);
    const int a_col = (lane >> 4) * 8;
    // B frag (x4 over n16): nrow = p*16 + (lane>>4)*8 + (lane&7),
    //                       kcol = ks*16 + ((lane>>3)&1)*8
    const int b_nrow = (lane >> 4) * 8 + (lane & 7);
    const int b_kcol = ((lane >> 3) & 1) * 8;

    float acc[4][4][4];
    #pragma unroll
    for (int i = 0; i < 4; i++)
        #pragma unroll
        for (int j = 0; j < 4; j++)
            #pragma unroll
            for (int e = 0; e < 4; e++) acc[i][j][e] = 0.0f;

    // ---- issue chunk 0 ----
    {
        const int kofs = 0;
        #pragma unroll
        for (int tl = 0; tl < 4; tl++) {
            const __nv_bfloat16* g0 = srcs[tl] + (size_t)(rb[tl] + r_lo) * K + kofs + c16 * 8;
            uint32_t s0 = sbase + tl * TILE_B + r_lo * (LDSS * 2) + c16 * 16;
            cp16(s0, g0);
            cp16(s0 + 64 * (LDSS * 2), g0 + (size_t)64 * K);
        }
    }
    CP_COMMIT();

    for (int i = 0; i < NC; i++) {
        const int buf = i & 1;
        if (i + 1 < NC) {
            const int kofs = (i + 1) * KC;
            const uint32_t bb = sbase + ((i + 1) & 1) * BUF_B;
            #pragma unroll
            for (int tl = 0; tl < 4; tl++) {
                const __nv_bfloat16* g0 = srcs[tl] + (size_t)(rb[tl] + r_lo) * K + kofs + c16 * 8;
                uint32_t s0 = bb + tl * TILE_B + r_lo * (LDSS * 2) + c16 * 16;
                cp16(s0, g0);
                cp16(s0 + 64 * (LDSS * 2), g0 + (size_t)64 * K);
            }
            CP_COMMIT();
            CP_WAIT(1);
        } else {
            CP_WAIT(0);
        }
        __syncthreads();

        const uint32_t bb = sbase + buf * BUF_B;
        const uint32_t baseAh = bb;
        const uint32_t baseAl = bb + TILE_B;
        const uint32_t baseBh = bb + 2 * TILE_B;
        const uint32_t baseBl = bb + 3 * TILE_B;

        #pragma unroll
        for (int ks = 0; ks < 2; ks++) {
            // B fragments for all 4 n8-tiles (2 x4 loads each for hi, lo)
            uint32_t bh[8], bl[8];
            #pragma unroll
            for (int p = 0; p < 2; p++) {
                uint32_t off = (uint32_t)(wn * 32 + p * 16 + b_nrow) * (LDSS * 2)
                             + (ks * 16 + b_kcol) * 2;
                ldm_x4(&bh[p * 4], baseBh + off);
                ldm_x4(&bl[p * 4], baseBl + off);
            }
            #pragma unroll
            for (int mt = 0; mt < 4; mt++) {
                uint32_t off = (uint32_t)(a_row + mt * 16) * (LDSS * 2)
                             + (ks * 16 + a_col) * 2;
                uint32_t ah[4], al[4];
                ldm_x4(ah, baseAh + off);
                ldm_x4(al, baseAl + off);
                #pragma unroll
                for (int nt = 0; nt < 4; nt++) {
                    mma_bf16(acc[mt][nt], ah, &bh[nt * 2]);
                    mma_bf16(acc[mt][nt], ah, &bl[nt * 2]);
                    mma_bf16(acc[mt][nt], al, &bh[nt * 2]);
                }
            }
        }
        __syncthreads();
    }

    // ---- epilogue ----
    const int qr = lane >> 2;            // 0..7
    const int qc = (lane & 3) * 2;       // 0,2,4,6
    #pragma unroll
    for (int mt = 0; mt < 4; mt++) {
        #pragma unroll
        for (int nt = 0; nt < 4; nt++) {
            const int gr0 = row0 + wm * 64 + mt * 16 + qr;
            const int gc  = col0 + wn * 32 + nt * 8 + qc;
            float2 bv = *(const float2*)(bias + gc);
            float o0 = acc[mt][nt][0] + bv.x;
            float o1 = acc[mt][nt][1] + bv.y;
            float o2 = acc[mt][nt][2] + bv.x;
            float o3 = acc[mt][nt][3] + bv.y;
            if (res) {
                float2 r0v = *(const float2*)(res + (size_t)gr0 * N + gc);
                float2 r1v = *(const float2*)(res + (size_t)(gr0 + 8) * N + gc);
                o0 += r0v.x; o1 += r0v.y; o2 += r1v.x; o3 += r1v.y;
            }
            if (do_gelu) {
                o0 = gelu_tanh(o0); o1 = gelu_tanh(o1);
                o2 = gelu_tanh(o2); o3 = gelu_tanh(o3);
            }
            *(float2*)(C + (size_t)gr0 * N + gc)       = make_float2(o0, o1);
            *(float2*)(C + (size_t)(gr0 + 8) * N + gc) = make_float2(o2, o3);
        }
    }
}

// ---------------------------------------------------------------------------
// Fused flash attention (fp32, online softmax)
// ---------------------------------------------------------------------------
#define ALD 68

__global__ __launch_bounds__(256)
void attn_kernel(const float* __restrict__ Q, const float* __restrict__ Kg,
                 const float* __restrict__ Vg, const int* __restrict__ mask,
                 float* __restrict__ O)
{
    extern __shared__ float smf[];
    float* Qs = smf;
    float* Ks = smf + 64 * ALD;
    float* Vs = smf + 2 * 64 * ALD;
    float* Ps = smf + 3 * 64 * ALD;

    const int t = threadIdx.x;
    const int b = blockIdx.z, h = blockIdx.y;
    const int q0 = blockIdx.x * 64;
    const int q    = t >> 2;
    const int part = t & 3;

    {
        const int i = t >> 2, d0 = (t & 3) * 16;
        const float* src = Q + ((size_t)(b * SEQ + q0 + i)) * HDIM + h * DHEAD + d0;
        #pragma unroll
        for (int j = 0; j < 16; j++) Qs[i * ALD + d0 + j] = src[j];
    }

    float acc[16];
    #pragma unroll
    for (int i = 0; i < 16; i++) acc[i] = 0.0f;
    float m_run = -1e30f, l_run = 0.0f;

    const int* mrow = mask + ((size_t)(b * SEQ + q0 + q)) * SEQ;

    for (int kc = 0; kc < SEQ; kc += 64) {
        __syncthreads();
        {
            const int i = t >> 2, d0 = (t & 3) * 16;
            const float* ks = Kg + ((size_t)(b * SEQ + kc + i)) * HDIM + h * DHEAD + d0;
            const float* vs = Vg + ((size_t)(b * SEQ + kc + i)) * HDIM + h * DHEAD + d0;
            #pragma unroll
            for (int j = 0; j < 16; j++) {
                Ks[i * ALD + d0 + j] = ks[j];
                Vs[i * ALD + d0 + j] = vs[j];
            }
        }
        __syncthreads();

        float s[16];
        #pragma unroll
        for (int kk = 0; kk < 16; kk++) s[kk] = 0.0f;
        #pragma unroll
        for (int d0 = 0; d0 < 64; d0 += 16) {
            float4 qv[4];
            #pragma unroll
            for (int u = 0; u < 4; u++)
                qv[u] = *(const float4*)&Qs[q * ALD + d0 + 4 * u];
            #pragma unroll
            for (int kk = 0; kk < 16; kk++) {
                const int k = part * 16 + kk;
                float p = 0.0f;
                #pragma unroll
                for (int u = 0; u < 4; u++) {
                    float4 kv = *(const float4*)&Ks[k * ALD + d0 + 4 * u];
                    p += qv[u].x * kv.x + qv[u].y * kv.y + qv[u].z * kv.z + qv[u].w * kv.w;
                }
                s[kk] += p;
            }
        }

        float cmax = -1e30f;
        #pragma unroll
        for (int kk = 0; kk < 16; kk++) {
            const int k = part * 16 + kk;
            float add = (1.0f - (float)mrow[kc + k]) * -10000.0f;
            s[kk] = s[kk] * 0.125f + add;
            cmax = fmaxf(cmax, s[kk]);
        }
        cmax = fmaxf(cmax, __shfl_xor_sync(0xffffffffu, cmax, 1));
        cmax = fmaxf(cmax, __shfl_xor_sync(0xffffffffu, cmax, 2));

        const float m_new = fmaxf(m_run, cmax);
        const float alpha = __expf(m_run - m_new);
        float psum = 0.0f;
        #pragma unroll
        for (int kk = 0; kk < 16; kk++) {
            float p = __expf(s[kk] - m_new);
            Ps[q * ALD + part * 16 + kk] = p;
            psum += p;
        }
        psum += __shfl_xor_sync(0xffffffffu, psum, 1);
        psum += __shfl_xor_sync(0xffffffffu, psum, 2);
        l_run = l_run * alpha + psum;
        m_run = m_new;
        __syncwarp();

        #pragma unroll
        for (int i = 0; i < 16; i++) acc[i] *= alpha;
        const int dbase = part * 16;
        #pragma unroll
        for (int k = 0; k < 64; k++) {
            const float p = Ps[q * ALD + k];
            #pragma unroll
            for (int u = 0; u < 4; u++) {
                float4 vv = *(const float4*)&Vs[k * ALD + dbase + 4 * u];
                acc[4 * u + 0] = fmaf(p, vv.x, acc[4 * u + 0]);
                acc[4 * u + 1] = fmaf(p, vv.y, acc[4 * u + 1]);
                acc[4 * u + 2] = fmaf(p, vv.z, acc[4 * u + 2]);
                acc[4 * u + 3] = fmaf(p, vv.w, acc[4 * u + 3]);
            }
        }
    }

    const float inv_l = 1.0f / l_run;
    float* dst = O + ((size_t)(b * SEQ + q0 + q)) * HDIM + h * DHEAD + part * 16;
    #pragma unroll
    for (int i = 0; i < 16; i++) dst[i] = acc[i] * inv_l;
}

// ---------------------------------------------------------------------------
// LayerNorm over rows of HDIM=1024
// ---------------------------------------------------------------------------
__global__ __launch_bounds__(256)
void ln_kernel(const float* __restrict__ x, const float* __restrict__ gamma,
               const float* __restrict__ beta, float* __restrict__ y)
{
    const int row = blockIdx.x;
    const int t = threadIdx.x;
    const float* xr = x + (size_t)row * HDIM;

    float4 v = *(const float4*)(xr + t * 4);
    float s  = v.x + v.y + v.z + v.w;
    float s2 = v.x * v.x + v.y * v.y + v.z * v.z + v.w * v.w;

    #pragma unroll
    for (int o = 16; o > 0; o >>= 1) {
        s  += __shfl_xor_sync(0xffffffffu, s, o);
        s2 += __shfl_xor_sync(0xffffffffu, s2, o);
    }
    __shared__ float ws[8], ws2[8];
    const int w = t >> 5, lane = t & 31;
    if (lane == 0) { ws[w] = s; ws2[w] = s2; }
    __syncthreads();

    float ts = 0.0f, ts2 = 0.0f;
    #pragma unroll
    for (int i = 0; i < 8; i++) { ts += ws[i]; ts2 += ws2[i]; }

    const float mean = ts * (1.0f / HDIM);
    const float var  = ts2 * (1.0f / HDIM) - mean * mean;
    const float rstd = rsqrtf(var + 1e-12f);

    float4 g  = *(const float4*)(gamma + t * 4);
    float4 bb = *(const float4*)(beta  + t * 4);
    float4 o;
    o.x = (v.x - mean) * rstd * g.x + bb.x;
    o.y = (v.y - mean) * rstd * g.y + bb.y;
    o.z = (v.z - mean) * rstd * g.z + bb.z;
    o.w = (v.w - mean) * rstd * g.w + bb.w;
    *(float4*)(y + (size_t)row * HDIM + t * 4) = o;
}

// ---------------------------------------------------------------------------
// Orchestration
// ---------------------------------------------------------------------------
extern "C" void kernel_launch(void* const* d_in, const int* in_sizes, int n_in,
                              void* d_out, int out_size)
{
    (void)in_sizes; (void)n_in; (void)out_size;

    const float* inp    = (const float*)d_in[0];
    const int*   mask   = (const int*)  d_in[1];
    const float* Wq     = (const float*)d_in[2];
    const float* bq     = (const float*)d_in[3];
    const float* Wk     = (const float*)d_in[4];
    const float* bk     = (const float*)d_in[5];
    const float* Wv     = (const float*)d_in[6];
    const float* bv     = (const float*)d_in[7];
    const float* Wao    = (const float*)d_in[8];
    const float* bao    = (const float*)d_in[9];
    const float* gamma1 = (const float*)d_in[10];
    const float* beta1  = (const float*)d_in[11];
    const float* Wi     = (const float*)d_in[12];
    const float* bi     = (const float*)d_in[13];
    const float* Wo     = (const float*)d_in[14];
    const float* bo     = (const float*)d_in[15];
    const float* gamma2 = (const float*)d_in[16];
    const float* beta2  = (const float*)d_in[17];
    float* out = (float*)d_out;

    float *q, *k, *v, *ctx, *t1, *attn, *inter;
    cudaGetSymbolAddress((void**)&q,     g_q);
    cudaGetSymbolAddress((void**)&k,     g_k);
    cudaGetSymbolAddress((void**)&v,     g_v);
    cudaGetSymbolAddress((void**)&ctx,   g_ctx);
    cudaGetSymbolAddress((void**)&t1,    g_t1);
    cudaGetSymbolAddress((void**)&attn,  g_attn);
    cudaGetSymbolAddress((void**)&inter, g_inter);

    __nv_bfloat16 *xh,*xl,*ch,*cl,*ah,*al,*ih,*il;
    __nv_bfloat16 *wqh,*wql,*wkh,*wkl,*wvh,*wvl,*waoh,*waol,*wih,*wil,*woh,*wol;
    cudaGetSymbolAddress((void**)&xh, g_xh);   cudaGetSymbolAddress((void**)&xl, g_xl);
    cudaGetSymbolAddress((void**)&ch, g_ch);   cudaGetSymbolAddress((void**)&cl, g_cl);
    cudaGetSymbolAddress((void**)&ah, g_ah);   cudaGetSymbolAddress((void**)&al, g_al);
    cudaGetSymbolAddress((void**)&ih, g_ih);   cudaGetSymbolAddress((void**)&il, g_il);
    cudaGetSymbolAddress((void**)&wqh, g_wqh); cudaGetSymbolAddress((void**)&wql, g_wql);
    cudaGetSymbolAddress((void**)&wkh, g_wkh); cudaGetSymbolAddress((void**)&wkl, g_wkl);
    cudaGetSymbolAddress((void**)&wvh, g_wvh); cudaGetSymbolAddress((void**)&wvl, g_wvl);
    cudaGetSymbolAddress((void**)&waoh, g_waoh); cudaGetSymbolAddress((void**)&waol, g_waol);
    cudaGetSymbolAddress((void**)&wih, g_wih); cudaGetSymbolAddress((void**)&wil, g_wil);
    cudaGetSymbolAddress((void**)&woh, g_woh); cudaGetSymbolAddress((void**)&wol, g_wol);

    const int ATTN_SMEM = 4 * 64 * ALD * (int)sizeof(float);
    cudaFuncSetAttribute(mma_gemm, cudaFuncAttributeMaxDynamicSharedMemorySize, GEMM_SMEM);
    cudaFuncSetAttribute(attn_kernel, cudaFuncAttributeMaxDynamicSharedMemorySize, ATTN_SMEM);

    dim3 blk256(256);
    dim3 tblk(32, 8);

    // weight transpose+split
    transpose_split_kernel<<<dim3(HDIM/32, HDIM/32), tblk>>>(Wq, wqh, wql, HDIM, HDIM);
    transpose_split_kernel<<<dim3(HDIM/32, HDIM/32), tblk>>>(Wk, wkh, wkl, HDIM, HDIM);
    transpose_split_kernel<<<dim3(HDIM/32, HDIM/32), tblk>>>(Wv, wvh, wvl, HDIM, HDIM);
    transpose_split_kernel<<<dim3(HDIM/32, HDIM/32), tblk>>>(Wao, waoh, waol, HDIM, HDIM);
    transpose_split_kernel<<<dim3(FFDIM/32, HDIM/32), tblk>>>(Wi, wih, wil, HDIM, FFDIM);
    transpose_split_kernel<<<dim3(HDIM/32, FFDIM/32), tblk>>>(Wo, woh, wol, FFDIM, HDIM);

    // split input
    const int nH4 = MROWS * HDIM / 4, nF4 = MROWS * FFDIM / 4;
    split_kernel<<<(nH4 + 255) / 256, blk256>>>(inp, xh, xl, nH4);

    // QKV projections
    dim3 gQ(HDIM / 128, MROWS / 128);
    mma_gemm<<<gQ, blk256, GEMM_SMEM>>>(xh, xl, wqh, wql, bq, nullptr, q, MROWS, HDIM, HDIM, 0);
    mma_gemm<<<gQ, blk256, GEMM_SMEM>>>(xh, xl, wkh, wkl, bk, nullptr, k, MROWS, HDIM, HDIM, 0);
    mma_gemm<<<gQ, blk256, GEMM_SMEM>>>(xh, xl, wvh, wvl, bv, nullptr, v, MROWS, HDIM, HDIM, 0);

    // attention
    attn_kernel<<<dim3(SEQ / 64, NHEAD, BATCH), blk256, ATTN_SMEM>>>(q, k, v, mask, ctx);

    // AO projection + residual, LN1
    split_kernel<<<(nH4 + 255) / 256, blk256>>>(ctx, ch, cl, nH4);
    mma_gemm<<<gQ, blk256, GEMM_SMEM>>>(ch, cl, waoh, waol, bao, inp, t1, MROWS, HDIM, HDIM, 0);
    ln_kernel<<<MROWS, blk256>>>(t1, gamma1, beta1, attn);

    // FFN
    split_kernel<<<(nH4 + 255) / 256, blk256>>>(attn, ah, al, nH4);
    dim3 gF1(FFDIM / 128, MROWS / 128);
    mma_gemm<<<gF1, blk256, GEMM_SMEM>>>(ah, al, wih, wil, bi, nullptr, inter, MROWS, FFDIM, HDIM, 1);
    split_kernel<<<(nF4 + 255) / 256, blk256>>>(inter, ih, il, nF4);
    mma_gemm<<<gQ, blk256, GEMM_SMEM>>>(ih, il, woh, wol, bo, attn, t1, MROWS, HDIM, FFDIM, 0);
    ln_kernel<<<MROWS, blk256>>>(t1, gamma2, beta2, out);
}